// round 14
// baseline (speedup 1.0000x reference)
#include <cuda_runtime.h>
#include <cuda_bf16.h>
#include <cstdint>

// Gather: out[g][row][j*32+k] = in[row][g*512 + j*64 + k]
//   out flat float4 idx i: g=i>>20, row=(i>>6)&16383, v=i&63
//   src (float4 units) = row*1024 + g*128 + (v>>3)*16 + (v&7)
//
// Software-pipelined variant of R10 (best avg ~44.6us): 8 items/thread,
// rotating 4-deep load buffer. Prime loads 0..3, then steady state
// {store k, load k+4} — keeps ~4 loads continuously in flight AND overlaps
// the store issue stream with outstanding loads (R10 pulses: 4 loads, then
// 4 stores, load pipe idle during the burst). Payload buffer stays 4x
// float4 -> ~30 regs, occupancy preserved.

#define GRID_BLOCKS 4096u
#define STRIDE      (GRID_BLOCKS * 256u)   // 2^20 float4s per sweep

__device__ __forceinline__ unsigned int src_of(unsigned int i)
{
    unsigned int g   = i >> 20;
    unsigned int row = (i >> 6) & 16383u;
    unsigned int v   = i & 63u;
    return row * 1024u + g * 128u + (v >> 3) * 16u + (v & 7u);
}

__global__ void __launch_bounds__(256)
fuse_slice_cat_kernel(const float4* __restrict__ in, float4* __restrict__ out)
{
    const unsigned int i0 = blockIdx.x * 256u + threadIdx.x;

    float4 r[4];

    // Prime: load items 0..3.
    #pragma unroll
    for (int k = 0; k < 4; ++k)
        r[k] = in[src_of(i0 + (unsigned)k * STRIDE)];

    // Steady state: store k, load k+4 into the freed slot.
    #pragma unroll
    for (int k = 0; k < 4; ++k) {
        float4 v = r[k];
        r[k] = in[src_of(i0 + (unsigned)(k + 4) * STRIDE)];
        out[i0 + (unsigned)k * STRIDE] = v;
    }

    // Drain: store items 4..7.
    #pragma unroll
    for (int k = 4; k < 8; ++k)
        out[i0 + (unsigned)k * STRIDE] = r[k - 4];
}

extern "C" void kernel_launch(void* const* d_in, const int* in_sizes, int n_in,
                              void* d_out, int out_size)
{
    const float4* in  = (const float4*)d_in[0];
    float4*       out = (float4*)d_out;

    // 2^23 float4s total; 8 per thread -> 4096 blocks of 256.
    fuse_slice_cat_kernel<<<GRID_BLOCKS, 256>>>(in, out);
}